// round 8
// baseline (speedup 1.0000x reference)
#include <cuda_runtime.h>
#include <cuda_fp16.h>
#include <mma.h>

using namespace nvcuda;

#define N_NODES   100000
#define N_EDGES   3200000
#define F_IN      128
#define HID       64
#define N_GRAPHS  256
#define N_CLASSES 8
#define NB        391            // ceil(N_NODES / 256)

// ---------------- scratch (static device globals; no runtime allocs) ----------------
__device__ int    g_indeg[N_NODES];
__device__ int    g_off[N_NODES];
__device__ int    g_cursor[N_NODES];
__device__ int    g_blocksum[NB];
__device__ float  g_dis[N_NODES];
__device__ int    g_csr[N_EDGES];
__device__ uint4  g_bufAh[(size_t)N_NODES * 8];           // fp16 scaled gemm output (gather source)
__device__ uint4  g_bufH[(size_t)N_NODES * 8];            // fp16 relu(gather1 + b1)  (gemm2 input)
__device__ float4 g_bufB4[(size_t)N_NODES * (HID / 4)];   // fp32 gather2 output (pool input)

// ---------------- init: zero indeg ----------------
__global__ void zinit_kernel() {
    int i = blockIdx.x * blockDim.x + threadIdx.x;
    if (i < N_NODES) g_indeg[i] = 0;
}

// ---------------- in-degree histogram over dst (4 edges/thread, int4 loads) ----------------
__global__ void hist_kernel(const int* __restrict__ ei) {
    int e = blockIdx.x * blockDim.x + threadIdx.x;
    if (e >= N_EDGES / 4) return;
    int4 dd = ((const int4*)(ei + N_EDGES))[e];
    atomicAdd(&g_indeg[dd.x], 1);
    atomicAdd(&g_indeg[dd.y], 1);
    atomicAdd(&g_indeg[dd.z], 1);
    atomicAdd(&g_indeg[dd.w], 1);
}

// ---------------- dis = rsqrt(indeg + 1) ----------------
__global__ void dis_kernel() {
    int i = blockIdx.x * blockDim.x + threadIdx.x;
    if (i < N_NODES) g_dis[i] = rsqrtf((float)(g_indeg[i] + 1));
}

// ---------------- exclusive scan of indeg -> off ----------------
__global__ void scan_local_kernel() {
    __shared__ int s[256];
    int i = blockIdx.x * 256 + threadIdx.x;
    int v = (i < N_NODES) ? g_indeg[i] : 0;
    s[threadIdx.x] = v;
    __syncthreads();
    for (int d = 1; d < 256; d <<= 1) {
        int t = (threadIdx.x >= d) ? s[threadIdx.x - d] : 0;
        __syncthreads();
        s[threadIdx.x] += t;
        __syncthreads();
    }
    if (i < N_NODES) g_off[i] = s[threadIdx.x] - v;
    if (threadIdx.x == 255) g_blocksum[blockIdx.x] = s[255];
}

__global__ void scan_sums_kernel() {
    __shared__ int s[512];
    int i = threadIdx.x;
    int v = (i < NB) ? g_blocksum[i] : 0;
    s[i] = v;
    __syncthreads();
    for (int d = 1; d < 512; d <<= 1) {
        int t = (i >= d) ? s[i - d] : 0;
        __syncthreads();
        s[i] += t;
        __syncthreads();
    }
    if (i < NB) g_blocksum[i] = s[i] - v;
}

__global__ void scan_add_kernel() {
    int i = blockIdx.x * 256 + threadIdx.x;
    if (i >= N_NODES) return;
    int o = g_off[i] + g_blocksum[blockIdx.x];
    g_off[i] = o;
    g_cursor[i] = o;
}

// ---------------- CSR fill (4 edges/thread, int4 loads) ----------------
__global__ void fill_kernel(const int* __restrict__ ei) {
    int e = blockIdx.x * blockDim.x + threadIdx.x;
    if (e >= N_EDGES / 4) return;
    int4 ss = ((const int4*)ei)[e];
    int4 dd = ((const int4*)(ei + N_EDGES))[e];
    g_csr[atomicAdd(&g_cursor[dd.x], 1)] = ss.x;
    g_csr[atomicAdd(&g_cursor[dd.y], 1)] = ss.y;
    g_csr[atomicAdd(&g_cursor[dd.z], 1)] = ss.z;
    g_csr[atomicAdd(&g_cursor[dd.w], 1)] = ss.w;
}

// ---------------- wmma GEMM: bufAh[n] = fp16( dis[n] * A[n] @ W ) ----------------
template<int K, bool A_IS_HALF>
__global__ void __launch_bounds__(128) gemm_wmma_kernel(const float* __restrict__ Af,
                                                        const float* __restrict__ W) {
    constexpr int ALD = K + 8;           // halves
    constexpr int WLD = 72;              // halves
    constexpr int A_BYTES   = 64 * ALD * 2;
    constexpr int OUT_BYTES = 64 * 64 * 4;
    constexpr int R1 = (A_BYTES > OUT_BYTES) ? A_BYTES : OUT_BYTES;
    __shared__ char s_mem[R1 + K * WLD * 2];

    __half* sA   = (__half*)s_mem;
    float*  sOut = (float*)s_mem;                 // aliases sA (sync-separated)
    __half* sW   = (__half*)(s_mem + R1);

    int tid = threadIdx.x;
    int block0 = blockIdx.x * 64;

    for (int i = tid; i < K * 64; i += 128) {
        int r = i >> 6, c = i & 63;
        sW[r * WLD + c] = __float2half(W[i]);
    }

    if (A_IS_HALF) {
        const uint4* src = g_bufH;
        for (int i = tid; i < 64 * (K / 8); i += 128) {
            int r = i / (K / 8), u = i % (K / 8);
            int gr = block0 + r; if (gr >= N_NODES) gr = N_NODES - 1;
            *(uint4*)(sA + r * ALD + u * 8) = src[(size_t)gr * (K / 8) + u];
        }
    } else {
        for (int i = tid; i < 64 * (K / 4); i += 128) {
            int r = i / (K / 4), c4 = i % (K / 4);
            int gr = block0 + r; if (gr >= N_NODES) gr = N_NODES - 1;
            float4 v = ((const float4*)(Af + (size_t)gr * K))[c4];
            __half* dst = sA + r * ALD + c4 * 4;
            dst[0] = __float2half(v.x); dst[1] = __float2half(v.y);
            dst[2] = __float2half(v.z); dst[3] = __float2half(v.w);
        }
    }
    __syncthreads();

    int warp = tid >> 5;
    int wrow = warp * 16;

    wmma::fragment<wmma::accumulator, 16, 16, 16, float> acc[4];
#pragma unroll
    for (int n = 0; n < 4; ++n) wmma::fill_fragment(acc[n], 0.0f);

    wmma::fragment<wmma::matrix_a, 16, 16, 16, __half, wmma::row_major> fa;
    wmma::fragment<wmma::matrix_b, 16, 16, 16, __half, wmma::row_major> fb;
#pragma unroll
    for (int kf = 0; kf < K / 16; ++kf) {
        wmma::load_matrix_sync(fa, sA + wrow * ALD + kf * 16, ALD);
#pragma unroll
        for (int n = 0; n < 4; ++n) {
            wmma::load_matrix_sync(fb, sW + kf * 16 * WLD + n * 16, WLD);
            wmma::mma_sync(acc[n], fa, fb, acc[n]);
        }
    }

    __syncthreads();
#pragma unroll
    for (int n = 0; n < 4; ++n)
        wmma::store_matrix_sync(sOut + wrow * 64 + n * 16, acc[n], 64, wmma::mem_row_major);
    __syncthreads();

    int r  = tid >> 1;
    int hf = tid & 1;
    int gr = block0 + r;
    if (gr < N_NODES) {
        float s = g_dis[gr];
        const float* row = sOut + r * 64 + hf * 32;
        union { uint4 u; __half2 h[4]; } pk;
#pragma unroll
        for (int q = 0; q < 4; ++q) {
#pragma unroll
            for (int p = 0; p < 4; ++p)
                pk.h[p] = __float22half2_rn(make_float2(row[q*8 + p*2] * s, row[q*8 + p*2 + 1] * s));
            g_bufAh[(size_t)gr * 8 + hf * 4 + q] = pk.u;
        }
    }
}

// ---------------- gather: warp-coop index fetch + 8-deep row MLP ----------------
__device__ __forceinline__ void acc_row(float* acc, uint4 v) {
    union { uint4 u; __half2 h[4]; } pk; pk.u = v;
#pragma unroll
    for (int p = 0; p < 4; ++p) {
        float2 f = __half22float2(pk.h[p]);
        acc[p * 2]     += f.x;
        acc[p * 2 + 1] += f.y;
    }
}

// MODE 1: g_bufH = fp16( relu(acc*dn + b1) )   (layer-1 -> gemm2 input)
// MODE 2: g_bufB4 = fp32( acc*dn )             (layer-2 -> pooling input)
template<int MODE>
__global__ void __launch_bounds__(256) gather_kernel(const float* __restrict__ b1) {
    int t = blockIdx.x * 256 + threadIdx.x;
    int n = t >> 3;                 // 8 threads/node
    if (n >= N_NODES) return;
    int lane = t & 7;
    int wl = threadIdx.x & 31;
    int gbase = wl & ~7;                            // group base lane in warp
    unsigned gmask = 0xFFu << gbase;                // per-group shfl mask

    int st  = g_off[n];
    int deg = g_indeg[n];
    float dn = g_dis[n];

    float acc[8];
#pragma unroll
    for (int p = 0; p < 8; ++p) acc[p] = 0.0f;
    acc_row(acc, g_bufAh[(size_t)n * 8 + lane]);    // self loop

    int j = 0;
    for (; j + 8 <= deg; j += 8) {
        int myidx = g_csr[st + j + lane];           // 8 coalesced indices per group
#pragma unroll
        for (int i = 0; i < 8; ++i) {
            int s = __shfl_sync(gmask, myidx, gbase + i);
            acc_row(acc, g_bufAh[(size_t)s * 8 + lane]);
        }
    }
    for (; j < deg; ++j) {
        int s = g_csr[st + j];
        acc_row(acc, g_bufAh[(size_t)s * 8 + lane]);
    }

    if (MODE == 1) {
        union { uint4 u; __half2 h[4]; } pk;
#pragma unroll
        for (int p = 0; p < 4; ++p) {
            float v0 = fmaxf(acc[p*2]     * dn + b1[lane*8 + p*2],     0.0f);
            float v1 = fmaxf(acc[p*2 + 1] * dn + b1[lane*8 + p*2 + 1], 0.0f);
            pk.h[p] = __float22half2_rn(make_float2(v0, v1));
        }
        g_bufH[(size_t)n * 8 + lane] = pk.u;
    } else {
        size_t ob = (size_t)n * 16 + lane * 2;
        g_bufB4[ob]     = make_float4(acc[0]*dn, acc[1]*dn, acc[2]*dn, acc[3]*dn);
        g_bufB4[ob + 1] = make_float4(acc[4]*dn, acc[5]*dn, acc[6]*dn, acc[7]*dn);
    }
}

// ---------------- fused pool + head: 1 block per graph, atomic-free ----------------
__global__ void __launch_bounds__(64) pool_head_kernel(const int* __restrict__ batch,
                                                       const float* __restrict__ b2,
                                                       const float* __restrict__ Wf1,
                                                       const float* __restrict__ bf1,
                                                       const float* __restrict__ Wf2,
                                                       const float* __restrict__ bf2,
                                                       float* __restrict__ out) {
    __shared__ int   s_bound[2];
    __shared__ float s_mean[HID];
    __shared__ float s_h1[32];

    int g = blockIdx.x;
    int c = threadIdx.x;

    if (c < 2) {
        int target = g + c;
        int lo = 0, hi = N_NODES;
        while (lo < hi) {
            int mid = (lo + hi) >> 1;
            if (batch[mid] < target) lo = mid + 1; else hi = mid;
        }
        s_bound[c] = lo;
    }
    __syncthreads();

    int start = s_bound[0];
    int end   = s_bound[1];
    const float* h = (const float*)g_bufB4;

    float acc = 0.0f;
    for (int n = start; n < end; ++n)
        acc += h[(size_t)n * HID + c];

    int cnt = end - start;
    s_mean[c] = (cnt > 0) ? (acc / (float)cnt + b2[c]) : 0.0f;
    __syncthreads();

    if (c < 32) {
        float h1 = bf1[c];
#pragma unroll
        for (int k = 0; k < HID; ++k) h1 += s_mean[k] * Wf1[k * 32 + c];
        s_h1[c] = fmaxf(h1, 0.0f);
    }
    __syncthreads();

    if (c < N_CLASSES) {
        float o = bf2[c];
#pragma unroll
        for (int k = 0; k < 32; ++k) o += s_h1[k] * Wf2[k * N_CLASSES + c];
        out[g * N_CLASSES + c] = o;
    }
}

// ---------------- launch ----------------
extern "C" void kernel_launch(void* const* d_in, const int* in_sizes, int n_in,
                              void* d_out, int out_size) {
    const float* x   = (const float*)d_in[0];
    const int*   ei  = (const int*)d_in[1];     // int32 (JAX x64 disabled)
    const int*   bat = (const int*)d_in[2];     // int32
    const float* W1  = (const float*)d_in[3];
    const float* b1  = (const float*)d_in[4];
    const float* W2  = (const float*)d_in[5];
    const float* b2  = (const float*)d_in[6];
    const float* Wf1 = (const float*)d_in[7];
    const float* bf1 = (const float*)d_in[8];
    const float* Wf2 = (const float*)d_in[9];
    const float* bf2 = (const float*)d_in[10];
    float* out = (float*)d_out;

    const int TB  = 256;
    const int gN  = (N_NODES + TB - 1) / TB;            // 391
    const int gE4 = (N_EDGES / 4 + TB - 1) / TB;        // 3125
    const int gW  = (N_NODES + 63) / 64;                // 1563 (wmma gemm)
    const int gG  = (N_NODES * 8 + TB - 1) / TB;        // 3125

    // fork/join resources (created per call, not destroyed during capture; no dev mem)
    cudaStream_t sB;
    cudaEvent_t evFork, evJoin;
    cudaStreamCreateWithFlags(&sB, cudaStreamNonBlocking);
    cudaEventCreateWithFlags(&evFork, cudaEventDisableTiming);
    cudaEventCreateWithFlags(&evJoin, cudaEventDisableTiming);

    // prefix: indeg
    zinit_kernel<<<gN, TB>>>();
    hist_kernel<<<gE4, TB>>>(ei);

    // fork: dis + GEMM1 on sB; CSR scan+fill on main
    cudaEventRecord(evFork, 0);
    cudaStreamWaitEvent(sB, evFork, 0);
    dis_kernel<<<gN, TB, 0, sB>>>();
    gemm_wmma_kernel<F_IN, false><<<gW, 128, 0, sB>>>(x, W1);
    cudaEventRecord(evJoin, sB);

    scan_local_kernel<<<gN, TB>>>();
    scan_sums_kernel<<<1, 512>>>();
    scan_add_kernel<<<gN, TB>>>();
    fill_kernel<<<gE4, TB>>>(ei);

    cudaStreamWaitEvent(0, evJoin, 0);

    // layer 1 aggregate (fused relu(+b1), fp16 out)
    gather_kernel<1><<<gG, TB>>>(b1);

    // layer 2
    gemm_wmma_kernel<HID, true><<<gW, 128>>>(nullptr, W2);
    gather_kernel<2><<<gG, TB>>>(b1);

    // pool + head
    pool_head_kernel<<<N_GRAPHS, 64>>>(bat, b2, Wf1, bf1, Wf2, bf2, out);
}

// round 9
// speedup vs baseline: 1.0256x; 1.0256x over previous
#include <cuda_runtime.h>
#include <cuda_fp16.h>
#include <mma.h>

using namespace nvcuda;

#define N_NODES   100000
#define N_EDGES   3200000
#define F_IN      128
#define HID       64
#define N_GRAPHS  256
#define N_CLASSES 8
#define NB        391            // ceil(N_NODES / 256)

// ---------------- scratch (static device globals; no runtime allocs) ----------------
__device__ int    g_indeg[N_NODES];
__device__ int    g_off[N_NODES];
__device__ int    g_cursor[N_NODES];
__device__ int    g_blocksum[NB];
__device__ float  g_dis[N_NODES];
__device__ int    g_csr[N_EDGES];
__device__ uint4  g_bufAh[(size_t)N_NODES * 8];   // fp16 scaled gemm output (gather source)
__device__ uint4  g_bufH[(size_t)N_NODES * 8];    // fp16 relu(gather1 + b1)  (gemm2 input)
__device__ float  g_pooled[N_GRAPHS * HID];       // fused pooling accumulator

// ---------------- init: zero indeg + pooled ----------------
__global__ void zinit_kernel() {
    int i = blockIdx.x * blockDim.x + threadIdx.x;
    if (i < N_NODES) g_indeg[i] = 0;
    if (i < N_GRAPHS * HID) g_pooled[i] = 0.0f;
}

// ---------------- in-degree histogram over dst (4 edges/thread, int4 loads) ----------------
__global__ void hist_kernel(const int* __restrict__ ei) {
    int e = blockIdx.x * blockDim.x + threadIdx.x;
    if (e >= N_EDGES / 4) return;
    int4 dd = ((const int4*)(ei + N_EDGES))[e];
    atomicAdd(&g_indeg[dd.x], 1);
    atomicAdd(&g_indeg[dd.y], 1);
    atomicAdd(&g_indeg[dd.z], 1);
    atomicAdd(&g_indeg[dd.w], 1);
}

// ---------------- dis = rsqrt(indeg + 1) ----------------
__global__ void dis_kernel() {
    int i = blockIdx.x * blockDim.x + threadIdx.x;
    if (i < N_NODES) g_dis[i] = rsqrtf((float)(g_indeg[i] + 1));
}

// ---------------- exclusive scan of indeg -> off ----------------
__global__ void scan_local_kernel() {
    __shared__ int s[256];
    int i = blockIdx.x * 256 + threadIdx.x;
    int v = (i < N_NODES) ? g_indeg[i] : 0;
    s[threadIdx.x] = v;
    __syncthreads();
    for (int d = 1; d < 256; d <<= 1) {
        int t = (threadIdx.x >= d) ? s[threadIdx.x - d] : 0;
        __syncthreads();
        s[threadIdx.x] += t;
        __syncthreads();
    }
    if (i < N_NODES) g_off[i] = s[threadIdx.x] - v;
    if (threadIdx.x == 255) g_blocksum[blockIdx.x] = s[255];
}

__global__ void scan_sums_kernel() {
    __shared__ int s[512];
    int i = threadIdx.x;
    int v = (i < NB) ? g_blocksum[i] : 0;
    s[i] = v;
    __syncthreads();
    for (int d = 1; d < 512; d <<= 1) {
        int t = (i >= d) ? s[i - d] : 0;
        __syncthreads();
        s[i] += t;
        __syncthreads();
    }
    if (i < NB) g_blocksum[i] = s[i] - v;
}

__global__ void scan_add_kernel() {
    int i = blockIdx.x * 256 + threadIdx.x;
    if (i >= N_NODES) return;
    int o = g_off[i] + g_blocksum[blockIdx.x];
    g_off[i] = o;
    g_cursor[i] = o;
}

// ---------------- CSR fill (4 edges/thread, int4 loads) ----------------
__global__ void fill_kernel(const int* __restrict__ ei) {
    int e = blockIdx.x * blockDim.x + threadIdx.x;
    if (e >= N_EDGES / 4) return;
    int4 ss = ((const int4*)ei)[e];
    int4 dd = ((const int4*)(ei + N_EDGES))[e];
    g_csr[atomicAdd(&g_cursor[dd.x], 1)] = ss.x;
    g_csr[atomicAdd(&g_cursor[dd.y], 1)] = ss.y;
    g_csr[atomicAdd(&g_cursor[dd.z], 1)] = ss.z;
    g_csr[atomicAdd(&g_cursor[dd.w], 1)] = ss.w;
}

// ---------------- wmma GEMM: bufAh[n] = fp16( dis[n] * A[n] @ W ) ----------------
template<int K, bool A_IS_HALF>
__global__ void __launch_bounds__(128) gemm_wmma_kernel(const float* __restrict__ Af,
                                                        const float* __restrict__ W) {
    constexpr int ALD = K + 8;           // halves
    constexpr int WLD = 72;              // halves
    constexpr int A_BYTES   = 64 * ALD * 2;
    constexpr int OUT_BYTES = 64 * 64 * 4;
    constexpr int R1 = (A_BYTES > OUT_BYTES) ? A_BYTES : OUT_BYTES;
    __shared__ char s_mem[R1 + K * WLD * 2];

    __half* sA   = (__half*)s_mem;
    float*  sOut = (float*)s_mem;                 // aliases sA (sync-separated)
    __half* sW   = (__half*)(s_mem + R1);

    int tid = threadIdx.x;
    int block0 = blockIdx.x * 64;

    for (int i = tid; i < K * 64; i += 128) {
        int r = i >> 6, c = i & 63;
        sW[r * WLD + c] = __float2half(W[i]);
    }

    if (A_IS_HALF) {
        const uint4* src = g_bufH;
        for (int i = tid; i < 64 * (K / 8); i += 128) {
            int r = i / (K / 8), u = i % (K / 8);
            int gr = block0 + r; if (gr >= N_NODES) gr = N_NODES - 1;
            *(uint4*)(sA + r * ALD + u * 8) = src[(size_t)gr * (K / 8) + u];
        }
    } else {
        for (int i = tid; i < 64 * (K / 4); i += 128) {
            int r = i / (K / 4), c4 = i % (K / 4);
            int gr = block0 + r; if (gr >= N_NODES) gr = N_NODES - 1;
            float4 v = ((const float4*)(Af + (size_t)gr * K))[c4];
            __half* dst = sA + r * ALD + c4 * 4;
            dst[0] = __float2half(v.x); dst[1] = __float2half(v.y);
            dst[2] = __float2half(v.z); dst[3] = __float2half(v.w);
        }
    }
    __syncthreads();

    int warp = tid >> 5;
    int wrow = warp * 16;

    wmma::fragment<wmma::accumulator, 16, 16, 16, float> acc[4];
#pragma unroll
    for (int n = 0; n < 4; ++n) wmma::fill_fragment(acc[n], 0.0f);

    wmma::fragment<wmma::matrix_a, 16, 16, 16, __half, wmma::row_major> fa;
    wmma::fragment<wmma::matrix_b, 16, 16, 16, __half, wmma::row_major> fb;
#pragma unroll
    for (int kf = 0; kf < K / 16; ++kf) {
        wmma::load_matrix_sync(fa, sA + wrow * ALD + kf * 16, ALD);
#pragma unroll
        for (int n = 0; n < 4; ++n) {
            wmma::load_matrix_sync(fb, sW + kf * 16 * WLD + n * 16, WLD);
            wmma::mma_sync(acc[n], fa, fb, acc[n]);
        }
    }

    __syncthreads();
#pragma unroll
    for (int n = 0; n < 4; ++n)
        wmma::store_matrix_sync(sOut + wrow * 64 + n * 16, acc[n], 64, wmma::mem_row_major);
    __syncthreads();

    int r  = tid >> 1;
    int hf = tid & 1;
    int gr = block0 + r;
    if (gr < N_NODES) {
        float s = g_dis[gr];
        const float* row = sOut + r * 64 + hf * 32;
        union { uint4 u; __half2 h[4]; } pk;
#pragma unroll
        for (int q = 0; q < 4; ++q) {
#pragma unroll
            for (int p = 0; p < 4; ++p)
                pk.h[p] = __float22half2_rn(make_float2(row[q*8 + p*2] * s, row[q*8 + p*2 + 1] * s));
            g_bufAh[(size_t)gr * 8 + hf * 4 + q] = pk.u;
        }
    }
}

// ---------------- gather (4-deep unroll, round-7 form) ----------------
__device__ __forceinline__ void acc_row(float* acc, uint4 v) {
    union { uint4 u; __half2 h[4]; } pk; pk.u = v;
#pragma unroll
    for (int p = 0; p < 4; ++p) {
        float2 f = __half22float2(pk.h[p]);
        acc[p * 2]     += f.x;
        acc[p * 2 + 1] += f.y;
    }
}

// MODE 1: g_bufH = fp16( relu(acc*dn + b1) )         (layer-1 -> gemm2 input)
// MODE 2: pooled[batch[n]] += acc*dn  (fused pooling) (layer-2 -> head input)
template<int MODE>
__global__ void __launch_bounds__(256) gather_kernel(const float* __restrict__ b1,
                                                     const int* __restrict__ batch) {
    int t = blockIdx.x * 256 + threadIdx.x;
    int n = t >> 3;                 // 8 threads/node; grid covers exactly N_NODES*8
    int lane = t & 7;

    int st  = g_off[n];
    int deg = g_indeg[n];
    float dn = g_dis[n];

    float acc[8];
#pragma unroll
    for (int p = 0; p < 8; ++p) acc[p] = 0.0f;
    acc_row(acc, g_bufAh[(size_t)n * 8 + lane]);      // self loop

    int j = 0;
    for (; j + 4 <= deg; j += 4) {
        int s0 = g_csr[st + j + 0];
        int s1 = g_csr[st + j + 1];
        int s2 = g_csr[st + j + 2];
        int s3 = g_csr[st + j + 3];
        uint4 v0 = g_bufAh[(size_t)s0 * 8 + lane];
        uint4 v1 = g_bufAh[(size_t)s1 * 8 + lane];
        uint4 v2 = g_bufAh[(size_t)s2 * 8 + lane];
        uint4 v3 = g_bufAh[(size_t)s3 * 8 + lane];
        acc_row(acc, v0); acc_row(acc, v1); acc_row(acc, v2); acc_row(acc, v3);
    }
    for (; j < deg; ++j) {
        int s0 = g_csr[st + j];
        acc_row(acc, g_bufAh[(size_t)s0 * 8 + lane]);
    }

    if (MODE == 1) {
        union { uint4 u; __half2 h[4]; } pk;
#pragma unroll
        for (int p = 0; p < 4; ++p) {
            float v0 = fmaxf(acc[p*2]     * dn + b1[lane*8 + p*2],     0.0f);
            float v1 = fmaxf(acc[p*2 + 1] * dn + b1[lane*8 + p*2 + 1], 0.0f);
            pk.h[p] = __float22half2_rn(make_float2(v0, v1));
        }
        g_bufH[(size_t)n * 8 + lane] = pk.u;
    } else {
        // fused pooling: warp covers 4 consecutive nodes (no tail: 800000 threads exactly)
#pragma unroll
        for (int p = 0; p < 8; ++p) acc[p] *= dn;
        int g = batch[n];
        unsigned eq = __match_any_sync(0xFFFFFFFFu, g);
        if (eq == 0xFFFFFFFFu) {
            // all 4 nodes in warp share graph g: fold groups 8 and 16 apart
#pragma unroll
            for (int p = 0; p < 8; ++p) {
                acc[p] += __shfl_xor_sync(0xFFFFFFFFu, acc[p], 8);
                acc[p] += __shfl_xor_sync(0xFFFFFFFFu, acc[p], 16);
            }
            if ((threadIdx.x & 31) < 8) {
#pragma unroll
                for (int p = 0; p < 8; ++p)
                    atomicAdd(&g_pooled[g * HID + lane * 8 + p], acc[p]);
            }
        } else {
            // graph boundary inside warp: per-lane atomics
#pragma unroll
            for (int p = 0; p < 8; ++p)
                atomicAdd(&g_pooled[g * HID + lane * 8 + p], acc[p]);
        }
    }
}

// ---------------- head: mean + b2, fc1(relu), fc2 -> out ----------------
__global__ void __launch_bounds__(64) head_kernel(const int* __restrict__ batch,
                                                  const float* __restrict__ b2,
                                                  const float* __restrict__ Wf1,
                                                  const float* __restrict__ bf1,
                                                  const float* __restrict__ Wf2,
                                                  const float* __restrict__ bf2,
                                                  float* __restrict__ out) {
    __shared__ int   s_bound[2];
    __shared__ float s_mean[HID];
    __shared__ float s_h1[32];

    int g = blockIdx.x;
    int c = threadIdx.x;

    if (c < 2) {
        int target = g + c;
        int lo = 0, hi = N_NODES;
        while (lo < hi) {
            int mid = (lo + hi) >> 1;
            if (batch[mid] < target) lo = mid + 1; else hi = mid;
        }
        s_bound[c] = lo;
    }
    __syncthreads();

    int cnt = s_bound[1] - s_bound[0];
    float invc = (cnt > 0) ? (1.0f / (float)cnt) : 0.0f;
    s_mean[c] = (cnt > 0) ? (g_pooled[g * HID + c] * invc + b2[c]) : 0.0f;
    __syncthreads();

    if (c < 32) {
        float h1 = bf1[c];
#pragma unroll
        for (int k = 0; k < HID; ++k) h1 += s_mean[k] * Wf1[k * 32 + c];
        s_h1[c] = fmaxf(h1, 0.0f);
    }
    __syncthreads();

    if (c < N_CLASSES) {
        float o = bf2[c];
#pragma unroll
        for (int k = 0; k < 32; ++k) o += s_h1[k] * Wf2[k * N_CLASSES + c];
        out[g * N_CLASSES + c] = o;
    }
}

// ---------------- launch ----------------
extern "C" void kernel_launch(void* const* d_in, const int* in_sizes, int n_in,
                              void* d_out, int out_size) {
    const float* x   = (const float*)d_in[0];
    const int*   ei  = (const int*)d_in[1];     // int32 (JAX x64 disabled)
    const int*   bat = (const int*)d_in[2];     // int32
    const float* W1  = (const float*)d_in[3];
    const float* b1  = (const float*)d_in[4];
    const float* W2  = (const float*)d_in[5];
    const float* b2  = (const float*)d_in[6];
    const float* Wf1 = (const float*)d_in[7];
    const float* bf1 = (const float*)d_in[8];
    const float* Wf2 = (const float*)d_in[9];
    const float* bf2 = (const float*)d_in[10];
    float* out = (float*)d_out;

    const int TB  = 256;
    const int gN  = (N_NODES + TB - 1) / TB;            // 391
    const int gE4 = (N_EDGES / 4 + TB - 1) / TB;        // 3125
    const int gW  = (N_NODES + 63) / 64;                // 1563 (wmma gemm)
    const int gG  = (N_NODES * 8) / TB;                 // 3125 exact

    // fork/join resources (created per call, not destroyed during capture; no dev mem)
    cudaStream_t sB;
    cudaEvent_t evFork, evJoin;
    cudaStreamCreateWithFlags(&sB, cudaStreamNonBlocking);
    cudaEventCreateWithFlags(&evFork, cudaEventDisableTiming);
    cudaEventCreateWithFlags(&evJoin, cudaEventDisableTiming);

    // prefix: indeg
    zinit_kernel<<<gN, TB>>>();
    hist_kernel<<<gE4, TB>>>(ei);

    // fork: dis + GEMM1 on sB; CSR scan+fill on main
    cudaEventRecord(evFork, 0);
    cudaStreamWaitEvent(sB, evFork, 0);
    dis_kernel<<<gN, TB, 0, sB>>>();
    gemm_wmma_kernel<F_IN, false><<<gW, 128, 0, sB>>>(x, W1);
    cudaEventRecord(evJoin, sB);

    scan_local_kernel<<<gN, TB>>>();
    scan_sums_kernel<<<1, 512>>>();
    scan_add_kernel<<<gN, TB>>>();
    fill_kernel<<<gE4, TB>>>(ei);

    cudaStreamWaitEvent(0, evJoin, 0);

    // layer 1 aggregate (fused relu(+b1), fp16 out)
    gather_kernel<1><<<gG, TB>>>(b1, bat);

    // layer 2
    gemm_wmma_kernel<HID, true><<<gW, 128>>>(nullptr, W2);
    gather_kernel<2><<<gG, TB>>>(b1, bat);   // fused pooling

    // head
    head_kernel<<<N_GRAPHS, 64>>>(bat, b2, Wf1, bf1, Wf2, bf2, out);
}

// round 10
// speedup vs baseline: 1.1015x; 1.0740x over previous
#include <cuda_runtime.h>
#include <cuda_fp16.h>
#include <mma.h>

using namespace nvcuda;

#define N_NODES   100000
#define N_EDGES   3200000
#define F_IN      128
#define HID       64
#define N_GRAPHS  256
#define N_CLASSES 8
#define NB        391            // ceil(N_NODES / 256)

// ---------------- scratch (static device globals; no runtime allocs) ----------------
__device__ int    g_indeg[N_NODES];
__device__ int    g_off[N_NODES];
__device__ int    g_cursor[N_NODES];
__device__ int    g_blocksum[NB];
__device__ float  g_dis[N_NODES];
__device__ int    g_csr[N_EDGES];
__device__ uint4  g_xh[(size_t)N_NODES * 16];     // fp16 x (128 halves/node)
__device__ __half g_w1h[F_IN * HID];
__device__ __half g_w2h[HID * HID];
__device__ uint4  g_bufAh[(size_t)N_NODES * 8];   // fp16 gemm output (gather source)
__device__ uint4  g_bufH[(size_t)N_NODES * 8];    // fp16 relu(gather1 + b1)  (gemm2 input)
__device__ float  g_pooled[N_GRAPHS * HID];       // fused pooling accumulator

// ---------------- stream-B prepass: W -> fp16 ----------------
__global__ void convw_kernel(const float* __restrict__ W1, const float* __restrict__ W2) {
    int i = blockIdx.x * blockDim.x + threadIdx.x;
    if (i < F_IN * HID) g_w1h[i] = __float2half(W1[i]);
    if (i < HID * HID) g_w2h[i] = __float2half(W2[i]);
}

// ---------------- stream-B prepass: x -> fp16 (8 floats/thread) ----------------
__global__ void xhalf_kernel(const float* __restrict__ x) {
    int i = blockIdx.x * blockDim.x + threadIdx.x;   // over N_NODES*16
    if (i >= N_NODES * 16) return;
    float4 a = ((const float4*)x)[(size_t)i * 2];
    float4 b = ((const float4*)x)[(size_t)i * 2 + 1];
    union { uint4 u; __half2 h[4]; } pk;
    pk.h[0] = __float22half2_rn(make_float2(a.x, a.y));
    pk.h[1] = __float22half2_rn(make_float2(a.z, a.w));
    pk.h[2] = __float22half2_rn(make_float2(b.x, b.y));
    pk.h[3] = __float22half2_rn(make_float2(b.z, b.w));
    g_xh[i] = pk.u;
}

// ---------------- init: zero indeg + pooled ----------------
__global__ void zinit_kernel() {
    int i = blockIdx.x * blockDim.x + threadIdx.x;
    if (i < N_NODES) g_indeg[i] = 0;
    if (i < N_GRAPHS * HID) g_pooled[i] = 0.0f;
}

// ---------------- in-degree histogram over dst (4 edges/thread, int4 loads) ----------------
__global__ void hist_kernel(const int* __restrict__ ei) {
    int e = blockIdx.x * blockDim.x + threadIdx.x;
    if (e >= N_EDGES / 4) return;
    int4 dd = ((const int4*)(ei + N_EDGES))[e];
    atomicAdd(&g_indeg[dd.x], 1);
    atomicAdd(&g_indeg[dd.y], 1);
    atomicAdd(&g_indeg[dd.z], 1);
    atomicAdd(&g_indeg[dd.w], 1);
}

// ---------------- dis = rsqrt(indeg + 1) ----------------
__global__ void dis_kernel() {
    int i = blockIdx.x * blockDim.x + threadIdx.x;
    if (i < N_NODES) g_dis[i] = rsqrtf((float)(g_indeg[i] + 1));
}

// ---------------- exclusive scan of indeg -> off ----------------
__global__ void scan_local_kernel() {
    __shared__ int s[256];
    int i = blockIdx.x * 256 + threadIdx.x;
    int v = (i < N_NODES) ? g_indeg[i] : 0;
    s[threadIdx.x] = v;
    __syncthreads();
    for (int d = 1; d < 256; d <<= 1) {
        int t = (threadIdx.x >= d) ? s[threadIdx.x - d] : 0;
        __syncthreads();
        s[threadIdx.x] += t;
        __syncthreads();
    }
    if (i < N_NODES) g_off[i] = s[threadIdx.x] - v;
    if (threadIdx.x == 255) g_blocksum[blockIdx.x] = s[255];
}

__global__ void scan_sums_kernel() {
    __shared__ int s[512];
    int i = threadIdx.x;
    int v = (i < NB) ? g_blocksum[i] : 0;
    s[i] = v;
    __syncthreads();
    for (int d = 1; d < 512; d <<= 1) {
        int t = (i >= d) ? s[i - d] : 0;
        __syncthreads();
        s[i] += t;
        __syncthreads();
    }
    if (i < NB) g_blocksum[i] = s[i] - v;
}

__global__ void scan_add_kernel() {
    int i = blockIdx.x * 256 + threadIdx.x;
    if (i >= N_NODES) return;
    int o = g_off[i] + g_blocksum[blockIdx.x];
    g_off[i] = o;
    g_cursor[i] = o;
}

// ---------------- CSR fill (4 edges/thread, int4 loads) ----------------
__global__ void fill_kernel(const int* __restrict__ ei) {
    int e = blockIdx.x * blockDim.x + threadIdx.x;
    if (e >= N_EDGES / 4) return;
    int4 ss = ((const int4*)ei)[e];
    int4 dd = ((const int4*)(ei + N_EDGES))[e];
    g_csr[atomicAdd(&g_cursor[dd.x], 1)] = ss.x;
    g_csr[atomicAdd(&g_cursor[dd.y], 1)] = ss.y;
    g_csr[atomicAdd(&g_cursor[dd.z], 1)] = ss.z;
    g_csr[atomicAdd(&g_cursor[dd.w], 1)] = ss.w;
}

// ---------------- wmma GEMM (all-fp16 inputs, vector loads) ----------------
// LAYER1: A = g_xh, W = g_w1h, epilogue stores RAW fp16 (dis applied in gather1)
// else  : A = g_bufH, W = g_w2h, epilogue scales by dis
template<int K, bool LAYER1>
__global__ void __launch_bounds__(128) gemm_wmma_kernel() {
    constexpr int ALD = K + 8;           // halves
    constexpr int WLD = 72;              // halves
    constexpr int RU  = K / 8;           // uint4 per A row
    constexpr int A_BYTES   = 64 * ALD * 2;
    constexpr int OUT_BYTES = 64 * 64 * 4;
    constexpr int R1 = (A_BYTES > OUT_BYTES) ? A_BYTES : OUT_BYTES;
    __shared__ char s_mem[R1 + K * WLD * 2];

    __half* sA   = (__half*)s_mem;
    float*  sOut = (float*)s_mem;                 // aliases sA (sync-separated)
    __half* sW   = (__half*)(s_mem + R1);

    int tid = threadIdx.x;
    int block0 = blockIdx.x * 64;

    // W: K*64 halves via uint4
    const uint4* wsrc = (const uint4*)(LAYER1 ? g_w1h : g_w2h);
    for (int j = tid; j < K * 64 / 8; j += 128) {
        int r = j >> 3, c8 = j & 7;
        *(uint4*)(sW + r * WLD + c8 * 8) = wsrc[j];
    }

    // A: 64 rows x K halves via uint4
    const uint4* asrc = LAYER1 ? g_xh : g_bufH;
    for (int j = tid; j < 64 * RU; j += 128) {
        int r = j / RU, u = j % RU;
        int gr = block0 + r; if (gr >= N_NODES) gr = N_NODES - 1;
        *(uint4*)(sA + r * ALD + u * 8) = asrc[(size_t)gr * RU + u];
    }
    __syncthreads();

    int warp = tid >> 5;
    int wrow = warp * 16;

    wmma::fragment<wmma::accumulator, 16, 16, 16, float> acc[4];
#pragma unroll
    for (int n = 0; n < 4; ++n) wmma::fill_fragment(acc[n], 0.0f);

    wmma::fragment<wmma::matrix_a, 16, 16, 16, __half, wmma::row_major> fa;
    wmma::fragment<wmma::matrix_b, 16, 16, 16, __half, wmma::row_major> fb;
#pragma unroll
    for (int kf = 0; kf < K / 16; ++kf) {
        wmma::load_matrix_sync(fa, sA + wrow * ALD + kf * 16, ALD);
#pragma unroll
        for (int n = 0; n < 4; ++n) {
            wmma::load_matrix_sync(fb, sW + kf * 16 * WLD + n * 16, WLD);
            wmma::mma_sync(acc[n], fa, fb, acc[n]);
        }
    }

    __syncthreads();
#pragma unroll
    for (int n = 0; n < 4; ++n)
        wmma::store_matrix_sync(sOut + wrow * 64 + n * 16, acc[n], 64, wmma::mem_row_major);
    __syncthreads();

    int r  = tid >> 1;
    int hf = tid & 1;
    int gr = block0 + r;
    if (gr < N_NODES) {
        float s = LAYER1 ? 1.0f : g_dis[gr];
        const float* row = sOut + r * 64 + hf * 32;
        union { uint4 u; __half2 h[4]; } pk;
#pragma unroll
        for (int q = 0; q < 4; ++q) {
#pragma unroll
            for (int p = 0; p < 4; ++p)
                pk.h[p] = __float22half2_rn(make_float2(row[q*8 + p*2] * s, row[q*8 + p*2 + 1] * s));
            g_bufAh[(size_t)gr * 8 + hf * 4 + q] = pk.u;
        }
    }
}

// ---------------- gather ----------------
__device__ __forceinline__ void acc_row(float* acc, uint4 v) {
    union { uint4 u; __half2 h[4]; } pk; pk.u = v;
#pragma unroll
    for (int p = 0; p < 4; ++p) {
        float2 f = __half22float2(pk.h[p]);
        acc[p * 2]     += f.x;
        acc[p * 2 + 1] += f.y;
    }
}
__device__ __forceinline__ void acc_row_fma(float* acc, uint4 v, float s) {
    union { uint4 u; __half2 h[4]; } pk; pk.u = v;
#pragma unroll
    for (int p = 0; p < 4; ++p) {
        float2 f = __half22float2(pk.h[p]);
        acc[p * 2]     += f.x * s;
        acc[p * 2 + 1] += f.y * s;
    }
}

// MODE 1: rows UNscaled -> acc += dis[s]*row[s]; out = fp16(relu(acc*dn + b1)) -> g_bufH
// MODE 2: rows pre-scaled -> plain adds; pooled[batch[n]] += acc*dn (fused pooling)
template<int MODE>
__global__ void __launch_bounds__(256) gather_kernel(const float* __restrict__ b1,
                                                     const int* __restrict__ batch) {
    int t = blockIdx.x * 256 + threadIdx.x;
    int n = t >> 3;                 // 8 threads/node; grid covers exactly N_NODES*8
    int lane = t & 7;

    int st  = g_off[n];
    int deg = g_indeg[n];
    float dn = g_dis[n];

    float acc[8];
#pragma unroll
    for (int p = 0; p < 8; ++p) acc[p] = 0.0f;
    // self loop
    if (MODE == 1) acc_row_fma(acc, g_bufAh[(size_t)n * 8 + lane], dn);
    else           acc_row(acc, g_bufAh[(size_t)n * 8 + lane]);

    int j = 0;
    for (; j + 8 <= deg; j += 8) {
        int sidx[8];
#pragma unroll
        for (int i = 0; i < 8; ++i) sidx[i] = g_csr[st + j + i];
        uint4 v[8];
#pragma unroll
        for (int i = 0; i < 8; ++i) v[i] = g_bufAh[(size_t)sidx[i] * 8 + lane];
        if (MODE == 1) {
            float ds[8];
#pragma unroll
            for (int i = 0; i < 8; ++i) ds[i] = g_dis[sidx[i]];
#pragma unroll
            for (int i = 0; i < 8; ++i) acc_row_fma(acc, v[i], ds[i]);
        } else {
#pragma unroll
            for (int i = 0; i < 8; ++i) acc_row(acc, v[i]);
        }
    }
    for (; j < deg; ++j) {
        int s = g_csr[st + j];
        if (MODE == 1) acc_row_fma(acc, g_bufAh[(size_t)s * 8 + lane], g_dis[s]);
        else           acc_row(acc, g_bufAh[(size_t)s * 8 + lane]);
    }

    if (MODE == 1) {
        union { uint4 u; __half2 h[4]; } pk;
#pragma unroll
        for (int p = 0; p < 4; ++p) {
            float v0 = fmaxf(acc[p*2]     * dn + b1[lane*8 + p*2],     0.0f);
            float v1 = fmaxf(acc[p*2 + 1] * dn + b1[lane*8 + p*2 + 1], 0.0f);
            pk.h[p] = __float22half2_rn(make_float2(v0, v1));
        }
        g_bufH[(size_t)n * 8 + lane] = pk.u;
    } else {
#pragma unroll
        for (int p = 0; p < 8; ++p) acc[p] *= dn;
        int g = batch[n];
        unsigned eq = __match_any_sync(0xFFFFFFFFu, g);
        if (eq == 0xFFFFFFFFu) {
#pragma unroll
            for (int p = 0; p < 8; ++p) {
                acc[p] += __shfl_xor_sync(0xFFFFFFFFu, acc[p], 8);
                acc[p] += __shfl_xor_sync(0xFFFFFFFFu, acc[p], 16);
            }
            if ((threadIdx.x & 31) < 8) {
#pragma unroll
                for (int p = 0; p < 8; ++p)
                    atomicAdd(&g_pooled[g * HID + lane * 8 + p], acc[p]);
            }
        } else {
#pragma unroll
            for (int p = 0; p < 8; ++p)
                atomicAdd(&g_pooled[g * HID + lane * 8 + p], acc[p]);
        }
    }
}

// ---------------- head: mean + b2, fc1(relu), fc2 -> out ----------------
__global__ void __launch_bounds__(64) head_kernel(const int* __restrict__ batch,
                                                  const float* __restrict__ b2,
                                                  const float* __restrict__ Wf1,
                                                  const float* __restrict__ bf1,
                                                  const float* __restrict__ Wf2,
                                                  const float* __restrict__ bf2,
                                                  float* __restrict__ out) {
    __shared__ int   s_bound[2];
    __shared__ float s_mean[HID];
    __shared__ float s_h1[32];

    int g = blockIdx.x;
    int c = threadIdx.x;

    if (c < 2) {
        int target = g + c;
        int lo = 0, hi = N_NODES;
        while (lo < hi) {
            int mid = (lo + hi) >> 1;
            if (batch[mid] < target) lo = mid + 1; else hi = mid;
        }
        s_bound[c] = lo;
    }
    __syncthreads();

    int cnt = s_bound[1] - s_bound[0];
    float invc = (cnt > 0) ? (1.0f / (float)cnt) : 0.0f;
    s_mean[c] = (cnt > 0) ? (g_pooled[g * HID + c] * invc + b2[c]) : 0.0f;
    __syncthreads();

    if (c < 32) {
        float h1 = bf1[c];
#pragma unroll
        for (int k = 0; k < HID; ++k) h1 += s_mean[k] * Wf1[k * 32 + c];
        s_h1[c] = fmaxf(h1, 0.0f);
    }
    __syncthreads();

    if (c < N_CLASSES) {
        float o = bf2[c];
#pragma unroll
        for (int k = 0; k < 32; ++k) o += s_h1[k] * Wf2[k * N_CLASSES + c];
        out[g * N_CLASSES + c] = o;
    }
}

// ---------------- launch ----------------
extern "C" void kernel_launch(void* const* d_in, const int* in_sizes, int n_in,
                              void* d_out, int out_size) {
    const float* x   = (const float*)d_in[0];
    const int*   ei  = (const int*)d_in[1];     // int32 (JAX x64 disabled)
    const int*   bat = (const int*)d_in[2];     // int32
    const float* W1  = (const float*)d_in[3];
    const float* b1  = (const float*)d_in[4];
    const float* W2  = (const float*)d_in[5];
    const float* b2  = (const float*)d_in[6];
    const float* Wf1 = (const float*)d_in[7];
    const float* bf1 = (const float*)d_in[8];
    const float* Wf2 = (const float*)d_in[9];
    const float* bf2 = (const float*)d_in[10];
    float* out = (float*)d_out;

    const int TB  = 256;
    const int gN  = (N_NODES + TB - 1) / TB;            // 391
    const int gE4 = (N_EDGES / 4 + TB - 1) / TB;        // 3125
    const int gW  = (N_NODES + 63) / 64;                // 1563 (wmma gemm)
    const int gG  = (N_NODES * 8) / TB;                 // 3125 exact
    const int gX  = (N_NODES * 16 + TB - 1) / TB;       // 6250

    // fork/join resources (created per call, not destroyed during capture; no dev mem)
    cudaStream_t sB;
    cudaEvent_t evFork, evJoin;
    cudaStreamCreateWithFlags(&sB, cudaStreamNonBlocking);
    cudaEventCreateWithFlags(&evFork, cudaEventDisableTiming);
    cudaEventCreateWithFlags(&evJoin, cudaEventDisableTiming);

    // fork immediately: stream B does x/W conversion + GEMM1 (independent of graph)
    cudaEventRecord(evFork, 0);
    cudaStreamWaitEvent(sB, evFork, 0);
    convw_kernel<<<(F_IN * HID + TB - 1) / TB, TB, 0, sB>>>(W1, W2);
    xhalf_kernel<<<gX, TB, 0, sB>>>(x);
    gemm_wmma_kernel<F_IN, true><<<gW, 128, 0, sB>>>();
    cudaEventRecord(evJoin, sB);

    // main: full CSR build
    zinit_kernel<<<gN, TB>>>();
    hist_kernel<<<gE4, TB>>>(ei);
    dis_kernel<<<gN, TB>>>();
    scan_local_kernel<<<gN, TB>>>();
    scan_sums_kernel<<<1, 512>>>();
    scan_add_kernel<<<gN, TB>>>();
    fill_kernel<<<gE4, TB>>>(ei);

    cudaStreamWaitEvent(0, evJoin, 0);

    // layer 1 aggregate (dis[s] FMA + fused relu(+b1), fp16 out)
    gather_kernel<1><<<gG, TB>>>(b1, bat);

    // layer 2
    gemm_wmma_kernel<HID, false><<<gW, 128>>>();
    gather_kernel<2><<<gG, TB>>>(b1, bat);   // fused pooling

    // head
    head_kernel<<<N_GRAPHS, 64>>>(bat, b2, Wf1, bf1, Wf2, bf2, out);
}